// round 16
// baseline (speedup 1.0000x reference)
#include <cuda_runtime.h>
#include <cstdint>

typedef unsigned long long u64;
typedef unsigned int u32;

#define NMAX      250048
#define PRE_NMS   6000
#define POST_NMS  300
#define CAP       32768
#define HI_CAP    4096
#define NBINS     8192
#define BIN_SH    19
#define IOU_THR   0.7f
#define IMG_H     1024.0f
#define IMG_W     1024.0f
#define STRIDE_F  16.0f
#define MCH       1024
#define MWORDS    16
#define GRID      256
#define BLK       256

// ---------------- device scratch (static, zero-init; self-cleaning per run) ----------------
__device__ u32    g_hist[NBINS];
__device__ u32    g_candCount;
__device__ u32    g_hiCount;
__device__ u32    g_score32[NMAX];   // slots >= N stay 0 forever
__device__ u64    g_cand[CAP];
__device__ u64    g_candHi[HI_CAP];
__device__ float4 g_sortedBoxes[PRE_NMS + 64];
__device__ __align__(16) u64 g_mask1024[MCH * MWORDS];
__device__ u64    g_nz[MWORDS];
__device__ u32    g_barCount;
__device__ u32    g_barGen;
__device__ u32    g_done;

// ---------------- helpers ----------------
__device__ __forceinline__ u32 flip_score(float s) {
    u32 u = __float_as_uint(s);
    return (u & 0x80000000u) ? ~u : (u | 0x80000000u);
}

__device__ __forceinline__ float4 decode_from(float4 a, float4 d) {
    float h = a.z - a.x;
    float w = a.w - a.y;
    float cy = a.x + 0.5f * h;
    float cx = a.y + 0.5f * w;
    float ncy = d.x * h + cy;
    float ncx = d.y * w + cx;
    float nh = expf(d.z) * h;
    float nw = expf(d.w) * w;
    float ymin = fminf(fmaxf(ncy - 0.5f * nh, 0.0f), IMG_H);
    float xmin = fminf(fmaxf(ncx - 0.5f * nw, 0.0f), IMG_W);
    float ymax = fminf(fmaxf(ncy + 0.5f * nh, 0.0f), IMG_H);
    float xmax = fminf(fmaxf(ncx + 0.5f * nw, 0.0f), IMG_W);
    return make_float4(ymin, xmin, ymax, xmax);
}

__device__ __forceinline__ float4 decode_box(const float* __restrict__ deltas,
                                             const float* __restrict__ anchors,
                                             int i) {
    float4 a = reinterpret_cast<const float4*>(anchors)[i];
    float4 d = reinterpret_cast<const float4*>(deltas)[i];
    return decode_from(a, d);
}

// grid barrier (all GRID blocks co-resident by launch_bounds(BLK,2), GRID<=296)
__device__ __forceinline__ void grid_bar(u32 target) {
    __syncthreads();
    if (threadIdx.x == 0) {
        __threadfence();
        u32 old = atomicAdd(&g_barCount, 1u);
        if (old == GRID - 1u) {
            g_barCount = 0u;
            __threadfence();
            atomicExch(&g_barGen, target);
        } else {
            u32 cur;
            for (;;) {
                asm volatile("ld.acquire.gpu.u32 %0, [%1];" : "=r"(cur) : "l"(&g_barGen) : "memory");
                if (cur >= target) break;
                __nanosleep(32);
            }
        }
        __threadfence();
    }
    __syncthreads();
}

// ---------------- the one kernel ----------------
__global__ void __launch_bounds__(BLK, 2)
rpn(const float* __restrict__ deltas,
    const float* __restrict__ anchors,
    const float* __restrict__ scores,
    float* __restrict__ out, int N) {
    // overlay: hist (32 KB) in phase A; boxes (20.5 KB) in phase E
    __shared__ __align__(16) char smemBuf[NBINS * 4];
    u32*    shist = (u32*)smemBuf;
    float4* sBox  = (float4*)smemBuf;
    float*  sArea = (float*)(smemBuf + MCH * sizeof(float4));
    __shared__ u32    ssum[BLK];
    __shared__ u32    sT13, sT13hi;
    __shared__ u32    sRowNz[4];
    __shared__ u32    sLast;
    __shared__ u64    sKeptMask[MWORDS];
    __shared__ u32    sKeptBase[MWORDS];
    __shared__ int    sKept;
    __shared__ float4 kb[POST_NMS];
    __shared__ float  karea[POST_NMS];
    __shared__ u64    sRed[BLK];

    const int t   = threadIdx.x;
    const int bid = blockIdx.x;

    // ===== Phase A: decode x4 + smem-private hist =====
    #pragma unroll
    for (int k = 0; k < NBINS / BLK; k++) shist[t + k * BLK] = 0u;
    __syncthreads();
    {
        int base = bid * (BLK * 4);
        #pragma unroll
        for (int k = 0; k < 4; k++) {
            int i = base + k * BLK + t;
            if (i < N) {
                float4 b = decode_box(deltas, anchors, i);
                bool valid = ((b.z - b.x) >= STRIDE_F) && ((b.w - b.y) >= STRIDE_F);
                u32 s = 0u;
                if (valid) { s = flip_score(scores[i]); atomicAdd(&shist[s >> BIN_SH], 1u); }
                g_score32[i] = s;
            }
        }
    }
    __syncthreads();
    #pragma unroll
    for (int k = 0; k < NBINS / BLK; k++) {
        u32 c = shist[t + k * BLK];
        if (c) atomicAdd(&g_hist[t + k * BLK], c);
    }
    grid_bar(1);

    // ===== Phase B: thresholds (computed redundantly by EVERY block) =====
    u32 t13, t13hi;
    {
        u32 sum = 0;
        const uint4* h4 = reinterpret_cast<const uint4*>(&g_hist[t << 5]);
        #pragma unroll
        for (int b = 0; b < 8; b++) { uint4 v = h4[b]; sum += v.x + v.y + v.z + v.w; }
        ssum[t] = sum;
        if (t == 0) { sT13 = 0u; sT13hi = 0u; }
        __syncthreads();
        for (int off = 1; off < BLK; off <<= 1) {
            u32 v = (t + off < BLK) ? ssum[t + off] : 0u;
            __syncthreads();
            ssum[t] += v;
            __syncthreads();
        }
        u32 myCum = ssum[t];
        u32 nxtCum = (t < BLK - 1) ? ssum[t + 1] : 0u;
        if (myCum >= PRE_NMS && nxtCum < PRE_NMS) {
            u32 running = nxtCum;
            for (int b = 31; b >= 0; b--) {
                running += g_hist[(t << 5) + b];
                if (running >= PRE_NMS) { sT13 = (u32)((t << 5) + b); break; }
            }
        }
        if (myCum >= MCH && nxtCum < MCH) {
            u32 running = nxtCum;
            for (int b = 31; b >= 0; b--) {
                running += g_hist[(t << 5) + b];
                if (running >= MCH) { sT13hi = (u32)((t << 5) + b); break; }
            }
        }
        __syncthreads();
        t13 = sT13;
        t13hi = sT13hi;
    }

    // ===== Phase C: compact (one uint4 per thread) =====
    {
        int idx = bid * BLK + t;                 // uint4 index
        if (idx < NMAX / 4) {
            uint4 s4 = *reinterpret_cast<const uint4*>(&g_score32[idx * 4]);
            #pragma unroll
            for (int q = 0; q < 4; q++) {
                u32 s = (q == 0) ? s4.x : (q == 1) ? s4.y : (q == 2) ? s4.z : s4.w;
                if (s != 0u) {
                    u32 bin = s >> BIN_SH;
                    if (bin >= t13) {
                        u64 key = ((u64)s << 32) | (u32)(~(u32)(idx * 4 + q));
                        u32 pos = atomicAdd(&g_candCount, 1u);
                        if (pos < CAP) g_cand[pos] = key;
                        if (bin >= t13hi) {
                            u32 hp = atomicAdd(&g_hiCount, 1u);
                            if (hp < HI_CAP) g_candHi[hp] = key;
                        }
                    }
                }
            }
        }
    }
    grid_bar(2);

    // ===== Phase D: rank hi set (warp per row) + fused scatter =====
    {
        u32 hiC = g_hiCount;
        const u64* __restrict__ src;
        int C;
        if (hiC <= HI_CAP) { src = g_candHi; C = (int)hiC; }
        else               { src = g_cand;   C = min((int)g_candCount, CAP); }
        int nwarps = GRID * (BLK / 32);
        int gw   = (bid * BLK + t) >> 5;
        int lane = t & 31;
        for (int r = gw; r < C; r += nwarps) {
            u64 myKey = __ldg(&src[r]);
            int cnt = 0;
            int c = lane;
            for (; c + 96 < C; c += 128) {
                u64 k0 = __ldg(&src[c]);
                u64 k1 = __ldg(&src[c + 32]);
                u64 k2 = __ldg(&src[c + 64]);
                u64 k3 = __ldg(&src[c + 96]);
                cnt += (k0 > myKey) + (k1 > myKey) + (k2 > myKey) + (k3 > myKey);
            }
            for (; c < C; c += 32) cnt += (__ldg(&src[c]) > myKey);
            #pragma unroll
            for (int off = 16; off > 0; off >>= 1)
                cnt += __shfl_down_sync(0xffffffffu, cnt, off);
            if (lane == 0 && cnt < PRE_NMS) {
                int idx = (int)(~(u32)(myKey & 0xFFFFFFFFull));
                g_sortedBoxes[cnt] = decode_box(deltas, anchors, idx);
            }
        }
    }
    grid_bar(3);

    // ===== Phase E: mask — 4 rows per block (threads 0..63) =====
    int n = min((int)g_candCount, PRE_NMS);
    u32 hiC = g_hiCount;
    int avail = (hiC <= HI_CAP) ? min(n, (int)hiC) : n;
    {
        if (t < 4) sRowNz[t] = 0u;
        for (int j = t; j < MCH; j += BLK) {
            float4 v = (j < avail) ? g_sortedBoxes[j] : make_float4(0.f, 0.f, 0.f, 0.f);
            sBox[j] = v;
            sArea[j] = (v.z - v.x) * (v.w - v.y);
        }
        __syncthreads();
        if (t < 64) {
            int r = t & 3;
            int w = t >> 2;
            int i = bid * 4 + r;
            u64 word = 0ull;
            int j0 = w << 6;
            if (i < avail && (j0 + 63) > i) {
                float4 bi = sBox[i];
                float  ai = sArea[i];
                #pragma unroll 8
                for (int bb = 0; bb < 64; bb++) {
                    int j = j0 + bb;
                    float4 bj = sBox[j];
                    float  aj = sArea[j];
                    float iy = fmaxf(0.0f, fminf(bi.z, bj.z) - fmaxf(bi.x, bj.x));
                    float ix = fmaxf(0.0f, fminf(bi.w, bj.w) - fmaxf(bi.y, bj.y));
                    float inter = iy * ix;
                    float iou = inter / (ai + aj - inter + 1e-9f);
                    if (iou > IOU_THR && j > i) word |= (1ull << bb);
                }
            }
            g_mask1024[(size_t)i * MWORDS + w] = word;
            if (word) atomicOr(&sRowNz[r], 1u);
        }
        __syncthreads();
        if (t < 4 && sRowNz[t]) {
            int row = bid * 4 + t;
            atomicOr(&g_nz[row >> 6], 1ull << (row & 63));
        }
    }

    // ===== arrival: last block proceeds to scan =====
    __syncthreads();
    if (t == 0) {
        __threadfence();
        u32 old = atomicAdd(&g_done, 1u);
        sLast = (old == GRID - 1u) ? 1u : 0u;
    }
    __syncthreads();
    if (!sLast) return;
    __threadfence();

    // ===== Phase F: word-skip scan + write-out (last block) =====
    int m = min(avail, MCH);
    if (t == 0) {
        u64 rem[MWORDS];
        #pragma unroll
        for (int k = 0; k < MWORDS; k++) rem[k] = 0ull;
        int kept = 0;
        int nw = (m + 63) >> 6;
        for (int wd = 0; wd < MWORDS; wd++) {
            if (wd >= nw || kept >= POST_NMS) { sKeptMask[wd] = 0ull; sKeptBase[wd] = (u32)kept; continue; }
            int nb = min(64, m - (wd << 6));
            u64 nz = g_nz[wd];
            u64 bad = rem[wd] | nz;
            u64 kmask;
            sKeptBase[wd] = (u32)kept;
            if (bad == 0ull && kept + nb <= POST_NMS) {
                kmask = (nb == 64) ? ~0ull : ((1ull << nb) - 1ull);
                kept += nb;
            } else {
                kmask = 0ull;
                for (int b = 0; b < nb && kept < POST_NMS; b++) {
                    if (!((rem[wd] >> b) & 1ull)) {
                        kmask |= (1ull << b);
                        kept++;
                        if ((nz >> b) & 1ull) {
                            const u64* row = &g_mask1024[(size_t)((wd << 6) + b) * MWORDS];
                            #pragma unroll
                            for (int k = 0; k < MWORDS; k++) rem[k] |= row[k];
                        }
                    }
                }
            }
            sKeptMask[wd] = kmask;
        }
        sKept = kept;
    }
    __syncthreads();
    int kept = sKept;

    for (int k = t; k < POST_NMS; k += BLK)
        if (k >= kept) reinterpret_cast<float4*>(out)[k] = make_float4(0.f, 0.f, 0.f, 0.f);
    for (int j = t; j < m; j += BLK) {
        int wd = j >> 6, b = j & 63;
        u64 km = sKeptMask[wd];
        if ((km >> b) & 1ull) {
            u64 below = (b == 0) ? 0ull : (km & ((1ull << b) - 1ull));
            int slot = (int)sKeptBase[wd] + __popcll(below);
            if (slot < POST_NMS)
                reinterpret_cast<float4*>(out)[slot] = g_sortedBoxes[j];
        }
    }

    // ---- fallback (never on bench data): selection-max over full candidate set ----
    if (kept < POST_NMS && n > m) {
        __syncthreads();
        for (int k = t; k < kept; k += BLK) {
            float4 b = reinterpret_cast<float4*>(out)[k];
            kb[k] = b;
            karea[k] = (b.z - b.x) * (b.w - b.y);
        }
        __syncthreads();
        int C = min((int)g_candCount, CAP);
        u64 prevKey = ~0ull;
        for (int step = 0; step < n && kept < POST_NMS; step++) {
            u64 best = 0ull;
            for (int c = t; c < C; c += BLK) {
                u64 k = g_cand[c];
                if (k < prevKey && k > best) best = k;
            }
            sRed[t] = best;
            __syncthreads();
            for (int off = BLK / 2; off > 0; off >>= 1) {
                if (t < off && sRed[t + off] > sRed[t]) sRed[t] = sRed[t + off];
                __syncthreads();
            }
            u64 sel = sRed[0];
            __syncthreads();
            if (sel == 0ull) break;
            prevKey = sel;
            if (step < m) continue;
            int idx = (int)(~(u32)(sel & 0xFFFFFFFFull));
            float4 b = decode_box(deltas, anchors, idx);
            float ab = (b.z - b.x) * (b.w - b.y);
            bool sup = false;
            for (int k = t; k < kept; k += BLK) {
                float4 c2 = kb[k];
                float  ac = karea[k];
                float iy = fmaxf(0.0f, fminf(b.z, c2.z) - fmaxf(b.x, c2.x));
                float ix = fmaxf(0.0f, fminf(b.w, c2.w) - fmaxf(b.y, c2.y));
                float inter = iy * ix;
                float iou = inter / (ab + ac - inter + 1e-9f);
                sup = sup || (iou > IOU_THR);
            }
            int any = __syncthreads_or((int)sup);
            if (!any) {
                if (t == 0) {
                    kb[kept] = b;
                    karea[kept] = ab;
                    reinterpret_cast<float4*>(out)[kept] = b;
                }
                kept++;
                __syncthreads();
            }
        }
    }

    // ---- cleanup: re-zero all per-run scratch (all other blocks have exited) ----
    __syncthreads();
    #pragma unroll
    for (int k = 0; k < NBINS / BLK; k++) g_hist[t + k * BLK] = 0u;
    if (t < MWORDS) g_nz[t] = 0ull;
    if (t == 0) {
        g_candCount = 0u;
        g_hiCount = 0u;
        g_barCount = 0u;
        __threadfence();
        atomicExch(&g_done, 0u);
        atomicExch(&g_barGen, 0u);
    }
}

// ---------------- launch ----------------
extern "C" void kernel_launch(void* const* d_in, const int* in_sizes, int n_in,
                              void* d_out, int out_size) {
    const float* deltas  = (const float*)d_in[0];
    const float* anchors = (const float*)d_in[1];
    const float* scores  = (const float*)d_in[2];
    int N = in_sizes[2];
    if (N > NMAX) N = NMAX;
    float* out = (float*)d_out;
    rpn<<<GRID, BLK>>>(deltas, anchors, scores, out, N);
}

// round 17
// speedup vs baseline: 1.0639x; 1.0639x over previous
#include <cuda_runtime.h>
#include <cstdint>

typedef unsigned long long u64;
typedef unsigned int u32;

#define NMAX      250048
#define PRE_NMS   6000
#define POST_NMS  300
#define CAP       32768
#define HI_CAP    4096
#define NBINS     4096          // top-12-bit bins (sign+exp+3 mantissa)
#define BIN_SH    20
#define IOU_THR   0.7f
#define IMG_H     1024.0f
#define IMG_W     1024.0f
#define STRIDE_F  16.0f
#define MCH       1024
#define MWORDS    16
#define GRID_C    256           // co-resident: launch_bounds(256,2) -> 296 slots

// ---------------- device scratch (static, zero-init; self-cleaning per run) ----------------
__device__ u32    g_hist[NBINS];
__device__ u32    g_t12;
__device__ u32    g_t12hi;
__device__ u32    g_candCount;
__device__ u32    g_hiCount;
__device__ u32    g_score32[NMAX];   // slots >= N stay 0 forever
__device__ u64    g_cand[CAP];
__device__ u64    g_candHi[HI_CAP];
__device__ float4 g_sortedBoxes[PRE_NMS + 64];
__device__ __align__(16) u64 g_mask1024[MCH * MWORDS];
__device__ u64    g_nz[MWORDS];
__device__ u32    g_syncA;
__device__ u32    g_barCount;
__device__ u32    g_barGen;
__device__ u32    g_doneC;

// ---------------- helpers ----------------
__device__ __forceinline__ u32 flip_score(float s) {
    u32 u = __float_as_uint(s);
    return (u & 0x80000000u) ? ~u : (u | 0x80000000u);
}

__device__ __forceinline__ float4 decode_from(float4 a, float4 d) {
    float h = a.z - a.x;
    float w = a.w - a.y;
    float cy = a.x + 0.5f * h;
    float cx = a.y + 0.5f * w;
    float ncy = d.x * h + cy;
    float ncx = d.y * w + cx;
    float nh = expf(d.z) * h;
    float nw = expf(d.w) * w;
    float ymin = fminf(fmaxf(ncy - 0.5f * nh, 0.0f), IMG_H);
    float xmin = fminf(fmaxf(ncx - 0.5f * nw, 0.0f), IMG_W);
    float ymax = fminf(fmaxf(ncy + 0.5f * nh, 0.0f), IMG_H);
    float xmax = fminf(fmaxf(ncx + 0.5f * nw, 0.0f), IMG_W);
    return make_float4(ymin, xmin, ymax, xmax);
}

__device__ __forceinline__ float4 decode_box(const float* __restrict__ deltas,
                                             const float* __restrict__ anchors,
                                             int i) {
    float4 a = reinterpret_cast<const float4*>(anchors)[i];
    float4 d = reinterpret_cast<const float4*>(deltas)[i];
    return decode_from(a, d);
}

// ---------------- KA: decode x2 + smem-private 4096-bin hist; last block -> thresholds ----------------
__global__ void kA(const float* __restrict__ deltas,
                   const float* __restrict__ anchors,
                   const float* __restrict__ scores, int N) {
    __shared__ u32 shist[NBINS];          // 16 KB
    __shared__ u32 ssum[512];
    __shared__ u32 sLast;
    int t = threadIdx.x;                  // 512
    #pragma unroll
    for (int k = 0; k < NBINS / 512; k++) shist[t + k * 512] = 0u;
    __syncthreads();

    int i0 = blockIdx.x * 1024 + t;
    int i1 = i0 + 512;
    const float4* a4 = reinterpret_cast<const float4*>(anchors);
    const float4* d4 = reinterpret_cast<const float4*>(deltas);

    bool v0 = i0 < N, v1 = i1 < N;
    float4 a0, d0, a1, d1;
    float  sc0 = 0.f, sc1 = 0.f;
    if (v0) { a0 = a4[i0]; d0 = d4[i0]; sc0 = scores[i0]; }
    if (v1) { a1 = a4[i1]; d1 = d4[i1]; sc1 = scores[i1]; }

    if (v0) {
        float4 b = decode_from(a0, d0);
        bool valid = ((b.z - b.x) >= STRIDE_F) && ((b.w - b.y) >= STRIDE_F);
        u32 s = 0u;
        if (valid) { s = flip_score(sc0); atomicAdd(&shist[s >> BIN_SH], 1u); }
        g_score32[i0] = s;
    }
    if (v1) {
        float4 b = decode_from(a1, d1);
        bool valid = ((b.z - b.x) >= STRIDE_F) && ((b.w - b.y) >= STRIDE_F);
        u32 s = 0u;
        if (valid) { s = flip_score(sc1); atomicAdd(&shist[s >> BIN_SH], 1u); }
        g_score32[i1] = s;
    }
    __syncthreads();

    #pragma unroll
    for (int k = 0; k < NBINS / 512; k++) {
        u32 c = shist[t + k * 512];
        if (c) atomicAdd(&g_hist[t + k * 512], c);
    }

    __syncthreads();
    if (t == 0) {
        __threadfence();
        u32 old = atomicAdd(&g_syncA, 1u);
        sLast = (old == gridDim.x - 1u) ? 1u : 0u;
    }
    __syncthreads();
    if (!sLast) return;
    __threadfence();

    // ---- threshold epilogue: thread t owns bins [8t, 8t+8) ----
    u32 bins[8];
    u32 sum = 0;
    const uint4* h4 = reinterpret_cast<const uint4*>(&g_hist[t << 3]);
    #pragma unroll
    for (int b = 0; b < 2; b++) {
        uint4 v = h4[b];
        bins[b * 4 + 0] = v.x; bins[b * 4 + 1] = v.y;
        bins[b * 4 + 2] = v.z; bins[b * 4 + 3] = v.w;
        sum += v.x + v.y + v.z + v.w;
    }
    ssum[t] = sum;
    __syncthreads();
    for (int off = 1; off < 512; off <<= 1) {
        u32 v = (t + off < 512) ? ssum[t + off] : 0u;
        __syncthreads();
        ssum[t] += v;
        __syncthreads();
    }
    u32 myCum = ssum[t];
    u32 nxtCum = (t < 511) ? ssum[t + 1] : 0u;
    if (myCum >= PRE_NMS && nxtCum < PRE_NMS) {
        u32 running = nxtCum;
        for (int b = 7; b >= 0; b--) {
            running += bins[b];
            if (running >= PRE_NMS) { g_t12 = (u32)((t << 3) + b); break; }
        }
    }
    if (myCum >= MCH && nxtCum < MCH) {
        u32 running = nxtCum;
        for (int b = 7; b >= 0; b--) {
            running += bins[b];
            if (running >= MCH) { g_t12hi = (u32)((t << 3) + b); break; }
        }
    }
    if (t == 0) {
        if (ssum[0] < PRE_NMS) g_t12 = 0u;
        if (ssum[0] < MCH)     g_t12hi = 0u;
    }
    __syncthreads();
    #pragma unroll
    for (int k = 0; k < NBINS / 512; k++) g_hist[t + (k << 9)] = 0u;
    if (t == 0) g_syncA = 0u;
}

// grid barrier for KC (GRID_C blocks, all co-resident)
__device__ __forceinline__ void grid_bar_c(u32 target) {
    __syncthreads();
    if (threadIdx.x == 0) {
        __threadfence();
        u32 old = atomicAdd(&g_barCount, 1u);
        if (old == GRID_C - 1u) {
            g_barCount = 0u;
            __threadfence();
            atomicExch(&g_barGen, target);
        } else {
            u32 cur;
            for (;;) {
                asm volatile("ld.acquire.gpu.u32 %0, [%1];" : "=r"(cur) : "l"(&g_barGen) : "memory");
                if (cur >= target) break;
                __nanosleep(32);
            }
        }
        __threadfence();
    }
    __syncthreads();
}

// ---------------- KC: compact(block-agg) -> bar -> rank+scatter -> bar -> mask -> scan ----------------
__global__ void __launch_bounds__(256, 2)
kC(const float* __restrict__ deltas,
   const float* __restrict__ anchors,
   float* __restrict__ out) {
    __shared__ float4 sBox[MCH];
    __shared__ float  sArea[MCH];
    __shared__ u32    sRowNz[4];
    __shared__ u32    sLast;
    __shared__ u32    sCnt, sCntHi, sBase, sBaseHi;
    __shared__ u64    sKeptMask[MWORDS];
    __shared__ u32    sKeptBase[MWORDS];
    __shared__ int    sKept;
    __shared__ float4 kb[POST_NMS];
    __shared__ float  karea[POST_NMS];
    __shared__ u64    sRed[256];

    int t = threadIdx.x;
    int bid = blockIdx.x;

    // ===== Phase 0: compact — smem-local slots, ONE global atomic per block per list =====
    {
        u32 thr   = g_t12;
        u32 thrHi = g_t12hi;
        if (t == 0) { sCnt = 0u; sCntHi = 0u; }
        __syncthreads();
        u64 keys[4];
        u32 loc[4], locHi[4];
        u32 hiFlags = 0u;
        int idx = bid * 256 + t;                 // uint4 index
        #pragma unroll
        for (int q = 0; q < 4; q++) keys[q] = 0ull;
        if (idx < NMAX / 4) {
            uint4 s4 = *reinterpret_cast<const uint4*>(&g_score32[idx * 4]);
            #pragma unroll
            for (int q = 0; q < 4; q++) {
                u32 s = (q == 0) ? s4.x : (q == 1) ? s4.y : (q == 2) ? s4.z : s4.w;
                if (s != 0u) {
                    u32 bin = s >> BIN_SH;
                    if (bin >= thr) {
                        keys[q] = ((u64)s << 32) | (u32)(~(u32)(idx * 4 + q));
                        loc[q] = atomicAdd(&sCnt, 1u);
                        if (bin >= thrHi) {
                            locHi[q] = atomicAdd(&sCntHi, 1u);
                            hiFlags |= (1u << q);
                        }
                    }
                }
            }
        }
        __syncthreads();
        if (t == 0) {
            sBase   = (sCnt   > 0u) ? atomicAdd(&g_candCount, sCnt)  : 0u;
            sBaseHi = (sCntHi > 0u) ? atomicAdd(&g_hiCount,  sCntHi) : 0u;
        }
        __syncthreads();
        #pragma unroll
        for (int q = 0; q < 4; q++) {
            if (keys[q] != 0ull) {
                u32 p = sBase + loc[q];
                if (p < CAP) g_cand[p] = keys[q];
                if (hiFlags & (1u << q)) {
                    u32 hp = sBaseHi + locHi[q];
                    if (hp < HI_CAP) g_candHi[hp] = keys[q];
                }
            }
        }
    }
    grid_bar_c(1);

    // ===== Phase 1: rank hi set (warp per row) + fused scatter =====
    {
        u32 hiC = g_hiCount;
        const u64* __restrict__ src;
        int C;
        if (hiC <= HI_CAP) { src = g_candHi; C = (int)hiC; }
        else               { src = g_cand;   C = min((int)g_candCount, CAP); }
        int nwarps = GRID_C * 8;
        int gw   = (bid * 256 + t) >> 5;
        int lane = t & 31;
        for (int r = gw; r < C; r += nwarps) {
            u64 myKey = __ldg(&src[r]);
            int cnt = 0;
            int c = lane;
            for (; c + 96 < C; c += 128) {
                u64 k0 = __ldg(&src[c]);
                u64 k1 = __ldg(&src[c + 32]);
                u64 k2 = __ldg(&src[c + 64]);
                u64 k3 = __ldg(&src[c + 96]);
                cnt += (k0 > myKey) + (k1 > myKey) + (k2 > myKey) + (k3 > myKey);
            }
            for (; c < C; c += 32) cnt += (__ldg(&src[c]) > myKey);
            #pragma unroll
            for (int off = 16; off > 0; off >>= 1)
                cnt += __shfl_down_sync(0xffffffffu, cnt, off);
            if (lane == 0 && cnt < PRE_NMS) {
                int idx = (int)(~(u32)(myKey & 0xFFFFFFFFull));
                g_sortedBoxes[cnt] = decode_box(deltas, anchors, idx);
            }
        }
    }
    grid_bar_c(2);

    // ===== Phase 2: mask — 4 rows per block (threads 0..63) =====
    int n = min((int)g_candCount, PRE_NMS);
    u32 hiC = g_hiCount;
    int avail = (hiC <= HI_CAP) ? min(n, (int)hiC) : n;
    {
        if (t < 4) sRowNz[t] = 0u;
        for (int j = t; j < MCH; j += 256) {
            float4 v = (j < avail) ? g_sortedBoxes[j] : make_float4(0.f, 0.f, 0.f, 0.f);
            sBox[j] = v;
            sArea[j] = (v.z - v.x) * (v.w - v.y);
        }
        __syncthreads();
        if (t < 64) {
            int r = t & 3;
            int w = t >> 2;
            int i = bid * 4 + r;
            u64 word = 0ull;
            int j0 = w << 6;
            if (i < avail && (j0 + 63) > i) {
                float4 bi = sBox[i];
                float  ai = sArea[i];
                #pragma unroll 8
                for (int bb = 0; bb < 64; bb++) {
                    int j = j0 + bb;
                    float4 bj = sBox[j];
                    float  aj = sArea[j];
                    float iy = fmaxf(0.0f, fminf(bi.z, bj.z) - fmaxf(bi.x, bj.x));
                    float ix = fmaxf(0.0f, fminf(bi.w, bj.w) - fmaxf(bi.y, bj.y));
                    float inter = iy * ix;
                    float iou = inter / (ai + aj - inter + 1e-9f);
                    if (iou > IOU_THR && j > i) word |= (1ull << bb);
                }
            }
            g_mask1024[(size_t)i * MWORDS + w] = word;
            if (word) atomicOr(&sRowNz[r], 1u);
        }
        __syncthreads();
        if (t < 4 && sRowNz[t]) {
            int row = bid * 4 + t;
            atomicOr(&g_nz[row >> 6], 1ull << (row & 63));
        }
    }

    // ===== arrival: last block proceeds to scan =====
    __syncthreads();
    if (t == 0) {
        __threadfence();
        u32 old = atomicAdd(&g_doneC, 1u);
        sLast = (old == GRID_C - 1u) ? 1u : 0u;
    }
    __syncthreads();
    if (!sLast) return;
    __threadfence();

    // ===== Phase 3: word-skip scan + write-out =====
    int m = min(avail, MCH);
    if (t == 0) {
        u64 rem[MWORDS];
        #pragma unroll
        for (int k = 0; k < MWORDS; k++) rem[k] = 0ull;
        int kept = 0;
        int nw = (m + 63) >> 6;
        for (int wd = 0; wd < MWORDS; wd++) {
            if (wd >= nw || kept >= POST_NMS) { sKeptMask[wd] = 0ull; sKeptBase[wd] = (u32)kept; continue; }
            int nb = min(64, m - (wd << 6));
            u64 nz = g_nz[wd];
            u64 bad = rem[wd] | nz;
            u64 kmask;
            sKeptBase[wd] = (u32)kept;
            if (bad == 0ull && kept + nb <= POST_NMS) {
                kmask = (nb == 64) ? ~0ull : ((1ull << nb) - 1ull);
                kept += nb;
            } else {
                kmask = 0ull;
                for (int b = 0; b < nb && kept < POST_NMS; b++) {
                    if (!((rem[wd] >> b) & 1ull)) {
                        kmask |= (1ull << b);
                        kept++;
                        if ((nz >> b) & 1ull) {
                            const u64* row = &g_mask1024[(size_t)((wd << 6) + b) * MWORDS];
                            #pragma unroll
                            for (int k = 0; k < MWORDS; k++) rem[k] |= row[k];
                        }
                    }
                }
            }
            sKeptMask[wd] = kmask;
        }
        sKept = kept;
    }
    __syncthreads();
    int kept = sKept;

    for (int k = t; k < POST_NMS; k += 256)
        if (k >= kept) reinterpret_cast<float4*>(out)[k] = make_float4(0.f, 0.f, 0.f, 0.f);
    for (int j = t; j < m; j += 256) {
        int wd = j >> 6, b = j & 63;
        u64 km = sKeptMask[wd];
        if ((km >> b) & 1ull) {
            u64 below = (b == 0) ? 0ull : (km & ((1ull << b) - 1ull));
            int slot = (int)sKeptBase[wd] + __popcll(below);
            if (slot < POST_NMS)
                reinterpret_cast<float4*>(out)[slot] = g_sortedBoxes[j];
        }
    }

    // ---- fallback (never on bench data): selection-max over full candidate set ----
    if (kept < POST_NMS && n > m) {
        __syncthreads();
        for (int k = t; k < kept; k += 256) {
            float4 b = reinterpret_cast<float4*>(out)[k];
            kb[k] = b;
            karea[k] = (b.z - b.x) * (b.w - b.y);
        }
        __syncthreads();
        int C = min((int)g_candCount, CAP);
        u64 prevKey = ~0ull;
        for (int step = 0; step < n && kept < POST_NMS; step++) {
            u64 best = 0ull;
            for (int c = t; c < C; c += 256) {
                u64 k = g_cand[c];
                if (k < prevKey && k > best) best = k;
            }
            sRed[t] = best;
            __syncthreads();
            for (int off = 128; off > 0; off >>= 1) {
                if (t < off && sRed[t + off] > sRed[t]) sRed[t] = sRed[t + off];
                __syncthreads();
            }
            u64 sel = sRed[0];
            __syncthreads();
            if (sel == 0ull) break;
            prevKey = sel;
            if (step < m) continue;
            int idx = (int)(~(u32)(sel & 0xFFFFFFFFull));
            float4 b = decode_box(deltas, anchors, idx);
            float ab = (b.z - b.x) * (b.w - b.y);
            bool sup = false;
            for (int k = t; k < kept; k += 256) {
                float4 c2 = kb[k];
                float  ac = karea[k];
                float iy = fmaxf(0.0f, fminf(b.z, c2.z) - fmaxf(b.x, c2.x));
                float ix = fmaxf(0.0f, fminf(b.w, c2.w) - fmaxf(b.y, c2.y));
                float inter = iy * ix;
                float iou = inter / (ab + ac - inter + 1e-9f);
                sup = sup || (iou > IOU_THR);
            }
            int any = __syncthreads_or((int)sup);
            if (!any) {
                if (t == 0) {
                    kb[kept] = b;
                    karea[kept] = ab;
                    reinterpret_cast<float4*>(out)[kept] = b;
                }
                kept++;
                __syncthreads();
            }
        }
    }

    // ---- re-zero per-run scratch ----
    __syncthreads();
    if (t < MWORDS) g_nz[t] = 0ull;
    if (t == 0) {
        g_candCount = 0u;
        g_hiCount = 0u;
        g_barCount = 0u;
        __threadfence();
        atomicExch(&g_doneC, 0u);
        atomicExch(&g_barGen, 0u);
    }
}

// ---------------- launch ----------------
extern "C" void kernel_launch(void* const* d_in, const int* in_sizes, int n_in,
                              void* d_out, int out_size) {
    const float* deltas  = (const float*)d_in[0];
    const float* anchors = (const float*)d_in[1];
    const float* scores  = (const float*)d_in[2];
    int N = in_sizes[2];
    if (N > NMAX) N = NMAX;
    float* out = (float*)d_out;

    kA<<<(N + 1023) / 1024, 512>>>(deltas, anchors, scores, N);
    kC<<<GRID_C, 256>>>(deltas, anchors, out);
}